// round 3
// baseline (speedup 1.0000x reference)
#include <cuda_runtime.h>
#include <cstdint>

#define S_TOK 2081
#define CATD 1024
#define NHEAD 16
#define HDIM 64
#define NCH 32
#define WW 65
#define MAXK 96

// ---------------- scratch (static device globals; no allocation) ----------------
__device__ float g_h[S_TOK * CATD];          // assembled token stream h
__device__ float g_qkv[S_TOK * 3 * CATD];    // q|k|v
__device__ float g_y[S_TOK * CATD];          // attention output (head-merged)
__device__ float g_yo[S_TOK * CATD];         // after W_o
__device__ float g_part[64 * 32 * CATD];     // split-K partials for comp GEMM

// ---------------- row maps ----------------
__device__ __forceinline__ int map_expand_c(int r) {
    // x row r -> h position: chunk c = r/64, j = r%64 -> c*65 + 1 + j
    return (r >> 6) * WW + 1 + (r & 63);
}
__device__ __forceinline__ int map_final_a(int r) {
    // output token r -> position in y
    if (r < 63) return r + 1;              // chunk 0, positions 1..63
    if (r == 2047) return 2080;            // last token
    int m = r - 63;                        // chunks 1..31, positions 0..63
    return ((m >> 6) + 1) * WW + (m & 63);
}

// ---------------- comp: fx = x.reshape(32,65536) @ W_comp  (split-K partials) ----------------
// grid (8 col-tiles of 128, 64 k-splits of 1024), 256 threads
__global__ void comp_kernel(const float* __restrict__ x, const float* __restrict__ Wc) {
    const int ct = blockIdx.x;
    const int ks = blockIdx.y;
    const int col0 = ct * 128;
    const int kbase = ks * 1024;
    __shared__ float As[32][33];
    __shared__ float Bs[32][128];
    const int tid = threadIdx.x;
    const int tr = tid >> 4;      // 0..15  -> rows tr*2, tr*2+1
    const int tc = tid & 15;      // 0..15  -> cols tc*8..tc*8+7
    float acc[2][8];
#pragma unroll
    for (int i = 0; i < 2; i++)
#pragma unroll
        for (int j = 0; j < 8; j++) acc[i][j] = 0.f;

    for (int k0 = 0; k0 < 1024; k0 += 32) {
        {   // A tile: 32 rows x 32 k
            int ar = tid >> 3;            // 0..31
            int ac = (tid & 7) << 2;      // 0..28
            float4 v = *(const float4*)(x + (size_t)ar * 65536 + kbase + k0 + ac);
            As[ac + 0][ar] = v.x; As[ac + 1][ar] = v.y;
            As[ac + 2][ar] = v.z; As[ac + 3][ar] = v.w;
        }
#pragma unroll
        for (int l = 0; l < 4; l++) {     // B tile: 32 k x 128 cols
            int idx = tid + l * 256;
            int br = idx >> 5;
            int bc = (idx & 31) << 2;
            *(float4*)&Bs[br][bc] =
                *(const float4*)(Wc + (size_t)(kbase + k0 + br) * 1024 + col0 + bc);
        }
        __syncthreads();
#pragma unroll
        for (int k = 0; k < 32; k++) {
            float a0 = As[k][tr * 2];
            float a1 = As[k][tr * 2 + 1];
            float4 b0 = *(float4*)&Bs[k][tc * 8];
            float4 b1 = *(float4*)&Bs[k][tc * 8 + 4];
            float bb[8] = {b0.x, b0.y, b0.z, b0.w, b1.x, b1.y, b1.z, b1.w};
#pragma unroll
            for (int j = 0; j < 8; j++) {
                acc[0][j] += a0 * bb[j];
                acc[1][j] += a1 * bb[j];
            }
        }
        __syncthreads();
    }
#pragma unroll
    for (int i = 0; i < 2; i++) {
        int row = tr * 2 + i;
        float* p = g_part + ((size_t)ks * 32 + row) * 1024 + col0 + tc * 8;
        *(float4*)p       = make_float4(acc[i][0], acc[i][1], acc[i][2], acc[i][3]);
        *(float4*)(p + 4) = make_float4(acc[i][4], acc[i][5], acc[i][6], acc[i][7]);
    }
}

// ---------------- reduce partials + bias into anchor rows of h ----------------
__global__ void comp_reduce(const float* __restrict__ b_comp, const float* __restrict__ dummy_fx) {
    int j = blockIdx.x;          // 0..32
    if (j == 32) {               // h[0] = dummy_fx
        for (int c = threadIdx.x; c < CATD; c += blockDim.x) g_h[c] = dummy_fx[c];
        return;
    }
    int row = (j + 1) * WW;      // comp[j] -> h[(j+1)*65]  (j=31 -> 2080)
    for (int c = threadIdx.x; c < CATD; c += blockDim.x) {
        float s = b_comp[c];
#pragma unroll 8
        for (int ks = 0; ks < 64; ks++)
            s += g_part[((size_t)ks * 32 + j) * 1024 + c];
        g_h[(size_t)row * CATD + c] = s;
    }
}

// ---------------- generic fp32 SGEMM, 128x128x16 tiles, 256 thr, 8x8/thread ----------------
// AMAP: 0=identity, 2=final-gather on A rows.  CMAP: 0=identity, 1=expand-scatter on C rows.
template <int AMAP, int CMAP>
__global__ void sgemm_kernel(const float* __restrict__ A, const float* __restrict__ B,
                             float* __restrict__ C, int M, int N, int K) {
    __shared__ float As[16][128];   // [k][m]
    __shared__ float Bs[16][128];   // [k][n]
    const int bx = blockIdx.x, by = blockIdx.y;
    const int tid = threadIdx.x;
    const int tr = tid >> 4;        // 0..15 -> rows tr*8..tr*8+7
    const int tc = tid & 15;        // 0..15 -> cols tc*8..tc*8+7
    float acc[8][8];
#pragma unroll
    for (int i = 0; i < 8; i++)
#pragma unroll
        for (int j = 0; j < 8; j++) acc[i][j] = 0.f;

    for (int k0 = 0; k0 < K; k0 += 16) {
#pragma unroll
        for (int l = 0; l < 2; l++) {   // A: 128 rows x 16 k
            int idx = tid + l * 256;
            int ar = idx >> 2;
            int ac = (idx & 3) << 2;
            int gr = by * 128 + ar;
            float4 v = make_float4(0.f, 0.f, 0.f, 0.f);
            if (gr < M) {
                int grm = (AMAP == 2) ? map_final_a(gr) : gr;
                v = *(const float4*)(A + (size_t)grm * K + k0 + ac);
            }
            As[ac + 0][ar] = v.x; As[ac + 1][ar] = v.y;
            As[ac + 2][ar] = v.z; As[ac + 3][ar] = v.w;
        }
#pragma unroll
        for (int l = 0; l < 2; l++) {   // B: 16 k x 128 n
            int idx = tid + l * 256;
            int br = idx >> 5;
            int bc = (idx & 31) << 2;
            *(float4*)&Bs[br][bc] =
                *(const float4*)(B + (size_t)(k0 + br) * N + bx * 128 + bc);
        }
        __syncthreads();
#pragma unroll
        for (int k = 0; k < 16; k++) {
            float4 a0 = *(float4*)&As[k][tr * 8];
            float4 a1 = *(float4*)&As[k][tr * 8 + 4];
            float4 b0 = *(float4*)&Bs[k][tc * 8];
            float4 b1 = *(float4*)&Bs[k][tc * 8 + 4];
            float a[8] = {a0.x, a0.y, a0.z, a0.w, a1.x, a1.y, a1.z, a1.w};
            float b[8] = {b0.x, b0.y, b0.z, b0.w, b1.x, b1.y, b1.z, b1.w};
#pragma unroll
            for (int i = 0; i < 8; i++)
#pragma unroll
                for (int j = 0; j < 8; j++)
                    acc[i][j] += a[i] * b[j];
        }
        __syncthreads();
    }
#pragma unroll
    for (int i = 0; i < 8; i++) {
        int gr = by * 128 + tr * 8 + i;
        if (gr >= M) continue;
        int grc = (CMAP == 1) ? map_expand_c(gr) : gr;
        float* cp = C + (size_t)grc * N + bx * 128 + tc * 8;
        *(float4*)cp       = make_float4(acc[i][0], acc[i][1], acc[i][2], acc[i][3]);
        *(float4*)(cp + 4) = make_float4(acc[i][4], acc[i][5], acc[i][6], acc[i][7]);
    }
}

// ---------------- rope (in place on q and k sections of g_qkv) ----------------
__global__ void rope_kernel(const float* __restrict__ cosb, const float* __restrict__ sinb) {
    int t = blockIdx.x * blockDim.x + threadIdx.x;
    if (t >= S_TOK * 2 * NHEAD * 32) return;
    int d = t & 31;  t >>= 5;
    int h = t & 15;  t >>= 4;
    int part = t & 1; t >>= 1;
    int s = t;
    float c1 = cosb[s * 64 + d],      s1 = sinb[s * 64 + d];
    float c2 = cosb[s * 64 + d + 32], s2 = sinb[s * 64 + d + 32];
    float* base = g_qkv + (size_t)s * 3072 + part * 1024 + h * 64;
    float t1 = base[d], t2 = base[d + 32];
    base[d]      = t1 * c1 - t2 * s1;
    base[d + 32] = t2 * c2 + t1 * s2;
}

// ---------------- attention: one block per (chunk, head); prefix-key list ----------------
// keys[idx]: idx < c -> anchor at idx*65 ; else window position c*65 + (idx - c)
// query qi (position c*65+qi) attends keys [0, c+qi] inclusive — contiguous prefix.
__global__ void attn_kernel() {
    extern __shared__ float sm[];
    const int c = blockIdx.x;     // 0..32
    const int h = blockIdx.y;
    const int nwin = (c == 32) ? 1 : WW;
    const int nk = c + nwin;
    const int nq = nwin;
    float* Ks = sm;                     // [96][65] padded
    float* Vs = Ks + MAXK * 65;         // [96][64]
    float* Qs = Vs + MAXK * 64;         // [4][64]
    float* Ps = Qs + 4 * 64;            // [4][96]
    const int tid = threadIdx.x, lane = tid & 31, w = tid >> 5;

    for (int e = tid; e < nk * 64; e += blockDim.x) {
        int kk = e >> 6, d = e & 63;
        int pos = (kk < c) ? kk * WW : c * WW + (kk - c);
        const float* src = g_qkv + (size_t)pos * 3072 + h * 64 + d;
        Ks[kk * 65 + d] = src[1024];
        Vs[kk * 64 + d] = src[2048];
    }
    __syncthreads();

    for (int qi = w; qi < nq; qi += 4) {
        int qpos = c * WW + qi;
        const float* qp = g_qkv + (size_t)qpos * 3072 + h * 64;
        Qs[w * 64 + lane]      = qp[lane];
        Qs[w * 64 + lane + 32] = qp[lane + 32];
        __syncwarp();
        int nv = c + qi + 1;
        float mx = -1e30f;
        for (int k = lane; k < nv; k += 32) {
            float s = 0.f;
#pragma unroll
            for (int d = 0; d < 64; d++) s += Qs[w * 64 + d] * Ks[k * 65 + d];
            s *= 0.125f;
            Ps[w * MAXK + k] = s;
            mx = fmaxf(mx, s);
        }
#pragma unroll
        for (int o = 16; o > 0; o >>= 1) mx = fmaxf(mx, __shfl_xor_sync(~0u, mx, o));
        float sum = 0.f;
        for (int k = lane; k < nv; k += 32) {
            float e = __expf(Ps[w * MAXK + k] - mx);
            Ps[w * MAXK + k] = e;
            sum += e;
        }
#pragma unroll
        for (int o = 16; o > 0; o >>= 1) sum += __shfl_xor_sync(~0u, sum, o);
        float inv = 1.0f / sum;
        __syncwarp();
        float a0 = 0.f, a1 = 0.f;
        for (int k = 0; k < nv; k++) {
            float p = Ps[w * MAXK + k];
            a0 += p * Vs[k * 64 + lane];
            a1 += p * Vs[k * 64 + lane + 32];
        }
        float* yp = g_y + (size_t)qpos * CATD + h * 64;
        yp[lane]      = a0 * inv;
        yp[lane + 32] = a1 * inv;
        __syncwarp();
    }
}

// ---------------- launch ----------------
static const int ATTN_SMEM = (MAXK * 65 + MAXK * 64 + 4 * 64 + 4 * MAXK) * 4;

extern "C" void kernel_launch(void* const* d_in, const int* in_sizes, int n_in,
                              void* d_out, int out_size) {
    const float* x        = (const float*)d_in[0];
    const float* W_expand = (const float*)d_in[1];
    const float* W_comp   = (const float*)d_in[2];
    const float* b_comp   = (const float*)d_in[3];
    const float* dummy_fx = (const float*)d_in[4];
    const float* W_qkv    = (const float*)d_in[5];
    const float* W_o      = (const float*)d_in[6];
    const float* W_final  = (const float*)d_in[7];
    const float* cosb     = (const float*)d_in[8];
    const float* sinb     = (const float*)d_in[9];
    float* out = (float*)d_out;

    float *h, *qkv, *y, *yo;
    cudaGetSymbolAddress((void**)&h,   g_h);
    cudaGetSymbolAddress((void**)&qkv, g_qkv);
    cudaGetSymbolAddress((void**)&y,   g_y);
    cudaGetSymbolAddress((void**)&yo,  g_yo);

    cudaFuncSetAttribute(attn_kernel, cudaFuncAttributeMaxDynamicSharedMemorySize, ATTN_SMEM);

    // 1) fx partials + reduce into anchor rows of h
    comp_kernel<<<dim3(8, 64), 256>>>(x, W_comp);
    comp_reduce<<<33, 256>>>(b_comp, dummy_fx);
    // 2) xe = x @ W_expand, scattered into h
    sgemm_kernel<0, 1><<<dim3(8, 16), 256>>>(x, W_expand, h, 2048, 1024, 1024);
    // 3) qkv = h @ W_qkv
    sgemm_kernel<0, 0><<<dim3(24, 17), 256>>>(h, W_qkv, qkv, S_TOK, 3072, 1024);
    // 4) rope on q,k
    rope_kernel<<<(S_TOK * 2 * NHEAD * 32 + 255) / 256, 256>>>(cosb, sinb);
    // 5) attention
    attn_kernel<<<dim3(33, NHEAD), 128, ATTN_SMEM>>>();
    // 6) y @ W_o
    sgemm_kernel<0, 0><<<dim3(8, 17), 256>>>(y, W_o, yo, S_TOK, 1024, 1024);
    // 7) gather + @ W_final -> out
    sgemm_kernel<2, 0><<<dim3(8, 16), 256>>>(yo, W_final, out, 2048, 1024, 1024);
}

// round 6
// speedup vs baseline: 1.3571x; 1.3571x over previous
#include <cuda_runtime.h>
#include <cstdint>

#define S_TOK 2081
#define CATD 1024
#define NHEAD 16
#define HDIM 64
#define NCH 32
#define WW 65
#define MAXK 96

// ---------------- scratch (static device globals; no allocation) ----------------
__device__ float g_h[S_TOK * CATD];          // assembled token stream h
__device__ float g_qkv[S_TOK * 3 * CATD];    // q|k|v
__device__ float g_y[S_TOK * CATD];          // attention output (head-merged)
__device__ float g_yo[S_TOK * CATD];         // after W_o
__device__ float g_part[64 * 32 * CATD];     // split-K partials for comp GEMM

// ---------------- row maps ----------------
__device__ __forceinline__ int map_expand_c(int r) {
    return (r >> 6) * WW + 1 + (r & 63);
}
__device__ __forceinline__ int map_final_a(int r) {
    if (r < 63) return r + 1;
    if (r == 2047) return 2080;
    int m = r - 63;
    return ((m >> 6) + 1) * WW + (m & 63);
}

// ---------------- async-copy helpers ----------------
__device__ __forceinline__ void cp16(float* dst, const float* src, bool pred) {
    uint32_t d = (uint32_t)__cvta_generic_to_shared(dst);
    int sz = pred ? 16 : 0;
    asm volatile("cp.async.cg.shared.global [%0], [%1], 16, %2;\n"
                 :: "r"(d), "l"(src), "r"(sz));
}
#define CP_COMMIT() asm volatile("cp.async.commit_group;\n" ::)
#define CP_WAIT0()  asm volatile("cp.async.wait_group 0;\n" ::)

// ---------------- tf32 mma ----------------
__device__ __forceinline__ void mma_tf32(float* c,
                                         uint32_t a0, uint32_t a1, uint32_t a2, uint32_t a3,
                                         uint32_t b0, uint32_t b1) {
    asm volatile(
        "mma.sync.aligned.m16n8k8.row.col.f32.tf32.tf32.f32 "
        "{%0,%1,%2,%3},{%4,%5,%6,%7},{%8,%9},{%0,%1,%2,%3};\n"
        : "+f"(c[0]), "+f"(c[1]), "+f"(c[2]), "+f"(c[3])
        : "r"(a0), "r"(a1), "r"(a2), "r"(a3), "r"(b0), "r"(b1));
}
__device__ __forceinline__ void split_tf32(float f, uint32_t& hi, uint32_t& lo) {
    uint32_t b = __float_as_uint(f);
    hi = b & 0xFFFFE000u;                       // tf32 truncation (what HW reads)
    lo = __float_as_uint(f - __uint_as_float(hi));  // exact residual
}

// ---------------- comp: fx = x.reshape(32,65536) @ W_comp  (split-K partials) ----------------
__global__ void comp_kernel(const float* __restrict__ x, const float* __restrict__ Wc) {
    const int ct = blockIdx.x;
    const int ks = blockIdx.y;
    const int col0 = ct * 128;
    const int kbase = ks * 1024;
    __shared__ float As[32][33];
    __shared__ float Bs[32][128];
    const int tid = threadIdx.x;
    const int tr = tid >> 4;
    const int tc = tid & 15;
    float acc[2][8];
#pragma unroll
    for (int i = 0; i < 2; i++)
#pragma unroll
        for (int j = 0; j < 8; j++) acc[i][j] = 0.f;

    for (int k0 = 0; k0 < 1024; k0 += 32) {
        {
            int ar = tid >> 3;
            int ac = (tid & 7) << 2;
            float4 v = *(const float4*)(x + (size_t)ar * 65536 + kbase + k0 + ac);
            As[ac + 0][ar] = v.x; As[ac + 1][ar] = v.y;
            As[ac + 2][ar] = v.z; As[ac + 3][ar] = v.w;
        }
#pragma unroll
        for (int l = 0; l < 4; l++) {
            int idx = tid + l * 256;
            int br = idx >> 5;
            int bc = (idx & 31) << 2;
            *(float4*)&Bs[br][bc] =
                *(const float4*)(Wc + (size_t)(kbase + k0 + br) * 1024 + col0 + bc);
        }
        __syncthreads();
#pragma unroll
        for (int k = 0; k < 32; k++) {
            float a0 = As[k][tr * 2];
            float a1 = As[k][tr * 2 + 1];
            float4 b0 = *(float4*)&Bs[k][tc * 8];
            float4 b1 = *(float4*)&Bs[k][tc * 8 + 4];
            float bb[8] = {b0.x, b0.y, b0.z, b0.w, b1.x, b1.y, b1.z, b1.w};
#pragma unroll
            for (int j = 0; j < 8; j++) {
                acc[0][j] += a0 * bb[j];
                acc[1][j] += a1 * bb[j];
            }
        }
        __syncthreads();
    }
#pragma unroll
    for (int i = 0; i < 2; i++) {
        int row = tr * 2 + i;
        float* p = g_part + ((size_t)ks * 32 + row) * 1024 + col0 + tc * 8;
        *(float4*)p       = make_float4(acc[i][0], acc[i][1], acc[i][2], acc[i][3]);
        *(float4*)(p + 4) = make_float4(acc[i][4], acc[i][5], acc[i][6], acc[i][7]);
    }
}

__global__ void comp_reduce(const float* __restrict__ b_comp, const float* __restrict__ dummy_fx) {
    int j = blockIdx.x;
    if (j == 32) {
        for (int c = threadIdx.x; c < CATD; c += blockDim.x) g_h[c] = dummy_fx[c];
        return;
    }
    int row = (j + 1) * WW;
    for (int c = threadIdx.x; c < CATD; c += blockDim.x) {
        float s = b_comp[c];
#pragma unroll 8
        for (int ks = 0; ks < 64; ks++)
            s += g_part[((size_t)ks * 32 + j) * 1024 + c];
        g_h[(size_t)row * CATD + c] = s;
    }
}

// ---------------- tf32 tensor-core GEMM, 128x128x32 tiles, 3-pass split ----------------
// AMAP: 0=identity, 2=final-gather on A rows.  CMAP: 0=identity, 1=expand-scatter on C rows.
#define SA 40      // As row stride (floats): [128][SA], 16B-aligned rows
#define SB 136     // Bs row stride (floats): [32][SB]
#define GEMM_SMEM ((2 * (128 * SA + 32 * SB)) * 4)

template <int AMAP, int CMAP>
__global__ void __launch_bounds__(256) tf32_gemm(const float* __restrict__ A,
                                                 const float* __restrict__ B,
                                                 float* __restrict__ C,
                                                 int M, int N, int K) {
    extern __shared__ float sm[];
    float* AsBase[2] = {sm, sm + 128 * SA};
    float* BsBase[2] = {sm + 2 * 128 * SA, sm + 2 * 128 * SA + 32 * SB};

    const int bx = blockIdx.x, by = blockIdx.y;
    const int tid = threadIdx.x;
    const int lane = tid & 31, wid = tid >> 5;
    const int warp_m = wid >> 2;     // 0..1 -> 64 rows
    const int warp_n = wid & 3;      // 0..3 -> 32 cols
    const int lr = lane >> 2, lk = lane & 3;

    float acc[4][4][4];
#pragma unroll
    for (int i = 0; i < 4; i++)
#pragma unroll
        for (int j = 0; j < 4; j++)
#pragma unroll
            for (int r = 0; r < 4; r++) acc[i][j][r] = 0.f;

    auto loadA = [&](int st, int k0) {
        float* As = AsBase[st];
#pragma unroll
        for (int l = 0; l < 4; l++) {
            int idx = tid + l * 256;
            int row = idx >> 3;
            int col = (idx & 7) << 2;
            int g = by * 128 + row;
            bool p = g < M;
            int grm = p ? ((AMAP == 2) ? map_final_a(g) : g) : 0;
            cp16(As + row * SA + col, A + (size_t)grm * K + k0 + col, p);
        }
    };
    auto loadB = [&](int st, int k0) {
        float* Bs = BsBase[st];
#pragma unroll
        for (int l = 0; l < 4; l++) {
            int idx = tid + l * 256;
            int kr = idx >> 5;
            int col = (idx & 31) << 2;
            cp16(Bs + kr * SB + col, B + (size_t)(k0 + kr) * N + bx * 128 + col, true);
        }
    };

    loadA(0, 0); loadB(0, 0); CP_COMMIT();

    const int ntiles = K >> 5;
    for (int kt = 0; kt < ntiles; kt++) {
        CP_WAIT0();
        __syncthreads();
        if (kt + 1 < ntiles) {
            loadA((kt + 1) & 1, (kt + 1) << 5);
            loadB((kt + 1) & 1, (kt + 1) << 5);
            CP_COMMIT();
        }
        const float* As = AsBase[kt & 1] + (warp_m * 64) * SA;
        const float* Bs = BsBase[kt & 1];
#pragma unroll
        for (int kk = 0; kk < 4; kk++) {
            // B fragments (hi/lo) for 4 n-tiles — conflict-free layout
            uint32_t bhi[4][2], blo[4][2];
#pragma unroll
            for (int nt = 0; nt < 4; nt++) {
                int n = warp_n * 32 + nt * 8 + lr;
                float b0 = Bs[(kk * 8 + lk) * SB + n];
                float b1 = Bs[(kk * 8 + lk + 4) * SB + n];
                split_tf32(b0, bhi[nt][0], blo[nt][0]);
                split_tf32(b1, bhi[nt][1], blo[nt][1]);
            }
#pragma unroll
            for (int mt = 0; mt < 4; mt++) {
                int m0 = mt * 16 + lr;
                float a0 = As[m0 * SA + kk * 8 + lk];
                float a1 = As[(m0 + 8) * SA + kk * 8 + lk];
                float a2 = As[m0 * SA + kk * 8 + lk + 4];
                float a3 = As[(m0 + 8) * SA + kk * 8 + lk + 4];
                uint32_t ah[4], al[4];
                split_tf32(a0, ah[0], al[0]);
                split_tf32(a1, ah[1], al[1]);
                split_tf32(a2, ah[2], al[2]);
                split_tf32(a3, ah[3], al[3]);
#pragma unroll
                for (int nt = 0; nt < 4; nt++) {
                    mma_tf32(acc[mt][nt], ah[0], ah[1], ah[2], ah[3], bhi[nt][0], bhi[nt][1]);
                    mma_tf32(acc[mt][nt], ah[0], ah[1], ah[2], ah[3], blo[nt][0], blo[nt][1]);
                    mma_tf32(acc[mt][nt], al[0], al[1], al[2], al[3], bhi[nt][0], bhi[nt][1]);
                }
            }
        }
        __syncthreads();
    }

    // epilogue
#pragma unroll
    for (int mt = 0; mt < 4; mt++) {
#pragma unroll
        for (int nt = 0; nt < 4; nt++) {
            int col = bx * 128 + warp_n * 32 + nt * 8 + lk * 2;
            int r0 = by * 128 + warp_m * 64 + mt * 16 + lr;
            int r1 = r0 + 8;
            if (r0 < M) {
                int rm = (CMAP == 1) ? map_expand_c(r0) : r0;
                *(float2*)(C + (size_t)rm * N + col) = make_float2(acc[mt][nt][0], acc[mt][nt][1]);
            }
            if (r1 < M) {
                int rm = (CMAP == 1) ? map_expand_c(r1) : r1;
                *(float2*)(C + (size_t)rm * N + col) = make_float2(acc[mt][nt][2], acc[mt][nt][3]);
            }
        }
    }
}

// ---------------- rope (in place on q and k sections of g_qkv) ----------------
__global__ void rope_kernel(const float* __restrict__ cosb, const float* __restrict__ sinb) {
    int t = blockIdx.x * blockDim.x + threadIdx.x;
    if (t >= S_TOK * 2 * NHEAD * 32) return;
    int d = t & 31;  t >>= 5;
    int h = t & 15;  t >>= 4;
    int part = t & 1; t >>= 1;
    int s = t;
    float c1 = cosb[s * 64 + d],      s1 = sinb[s * 64 + d];
    float c2 = cosb[s * 64 + d + 32], s2 = sinb[s * 64 + d + 32];
    float* base = g_qkv + (size_t)s * 3072 + part * 1024 + h * 64;
    float t1 = base[d], t2 = base[d + 32];
    base[d]      = t1 * c1 - t2 * s1;
    base[d + 32] = t2 * c2 + t1 * s2;
}

// ---------------- attention ----------------
__global__ void attn_kernel() {
    extern __shared__ float sm[];
    const int c = blockIdx.x;
    const int h = blockIdx.y;
    const int nwin = (c == 32) ? 1 : WW;
    const int nk = c + nwin;
    const int nq = nwin;
    float* Ks = sm;
    float* Vs = Ks + MAXK * 65;
    float* Qs = Vs + MAXK * 64;
    float* Ps = Qs + 4 * 64;
    const int tid = threadIdx.x, lane = tid & 31, w = tid >> 5;

    for (int e = tid; e < nk * 64; e += blockDim.x) {
        int kk = e >> 6, d = e & 63;
        int pos = (kk < c) ? kk * WW : c * WW + (kk - c);
        const float* src = g_qkv + (size_t)pos * 3072 + h * 64 + d;
        Ks[kk * 65 + d] = src[1024];
        Vs[kk * 64 + d] = src[2048];
    }
    __syncthreads();

    for (int qi = w; qi < nq; qi += 4) {
        int qpos = c * WW + qi;
        const float* qp = g_qkv + (size_t)qpos * 3072 + h * 64;
        Qs[w * 64 + lane]      = qp[lane];
        Qs[w * 64 + lane + 32] = qp[lane + 32];
        __syncwarp();
        int nv = c + qi + 1;
        float mx = -1e30f;
        for (int k = lane; k < nv; k += 32) {
            float s = 0.f;
#pragma unroll
            for (int d = 0; d < 64; d++) s += Qs[w * 64 + d] * Ks[k * 65 + d];
            s *= 0.125f;
            Ps[w * MAXK + k] = s;
            mx = fmaxf(mx, s);
        }
#pragma unroll
        for (int o = 16; o > 0; o >>= 1) mx = fmaxf(mx, __shfl_xor_sync(~0u, mx, o));
        float sum = 0.f;
        for (int k = lane; k < nv; k += 32) {
            float e = __expf(Ps[w * MAXK + k] - mx);
            Ps[w * MAXK + k] = e;
            sum += e;
        }
#pragma unroll
        for (int o = 16; o > 0; o >>= 1) sum += __shfl_xor_sync(~0u, sum, o);
        float inv = 1.0f / sum;
        __syncwarp();
        float a0 = 0.f, a1 = 0.f;
        for (int k = 0; k < nv; k++) {
            float p = Ps[w * MAXK + k];
            a0 += p * Vs[k * 64 + lane];
            a1 += p * Vs[k * 64 + lane + 32];
        }
        float* yp = g_y + (size_t)qpos * CATD + h * 64;
        yp[lane]      = a0 * inv;
        yp[lane + 32] = a1 * inv;
        __syncwarp();
    }
}

// ---------------- launch ----------------
static const int ATTN_SMEM = (MAXK * 65 + MAXK * 64 + 4 * 64 + 4 * MAXK) * 4;

extern "C" void kernel_launch(void* const* d_in, const int* in_sizes, int n_in,
                              void* d_out, int out_size) {
    const float* x        = (const float*)d_in[0];
    const float* W_expand = (const float*)d_in[1];
    const float* W_comp   = (const float*)d_in[2];
    const float* b_comp   = (const float*)d_in[3];
    const float* dummy_fx = (const float*)d_in[4];
    const float* W_qkv    = (const float*)d_in[5];
    const float* W_o      = (const float*)d_in[6];
    const float* W_final  = (const float*)d_in[7];
    const float* cosb     = (const float*)d_in[8];
    const float* sinb     = (const float*)d_in[9];
    float* out = (float*)d_out;

    float *h, *qkv, *y, *yo;
    cudaGetSymbolAddress((void**)&h,   g_h);
    cudaGetSymbolAddress((void**)&qkv, g_qkv);
    cudaGetSymbolAddress((void**)&y,   g_y);
    cudaGetSymbolAddress((void**)&yo,  g_yo);

    cudaFuncSetAttribute(attn_kernel, cudaFuncAttributeMaxDynamicSharedMemorySize, ATTN_SMEM);
    cudaFuncSetAttribute(tf32_gemm<0, 0>, cudaFuncAttributeMaxDynamicSharedMemorySize, GEMM_SMEM);
    cudaFuncSetAttribute(tf32_gemm<0, 1>, cudaFuncAttributeMaxDynamicSharedMemorySize, GEMM_SMEM);
    cudaFuncSetAttribute(tf32_gemm<2, 0>, cudaFuncAttributeMaxDynamicSharedMemorySize, GEMM_SMEM);

    // 1) fx partials + reduce into anchor rows of h
    comp_kernel<<<dim3(8, 64), 256>>>(x, W_comp);
    comp_reduce<<<33, 256>>>(b_comp, dummy_fx);
    // 2) xe = x @ W_expand, scattered into h
    tf32_gemm<0, 1><<<dim3(8, 16), 256, GEMM_SMEM>>>(x, W_expand, h, 2048, 1024, 1024);
    // 3) qkv = h @ W_qkv
    tf32_gemm<0, 0><<<dim3(24, 17), 256, GEMM_SMEM>>>(h, W_qkv, qkv, S_TOK, 3072, 1024);
    // 4) rope on q,k
    rope_kernel<<<(S_TOK * 2 * NHEAD * 32 + 255) / 256, 256>>>(cosb, sinb);
    // 5) attention
    attn_kernel<<<dim3(33, NHEAD), 128, ATTN_SMEM>>>();
    // 6) y @ W_o
    tf32_gemm<0, 0><<<dim3(8, 17), 256, GEMM_SMEM>>>(y, W_o, yo, S_TOK, 1024, 1024);
    // 7) gather + @ W_final -> out
    tf32_gemm<2, 0><<<dim3(8, 16), 256, GEMM_SMEM>>>(yo, W_final, out, 2048, 1024, 1024);
}